// round 9
// baseline (speedup 1.0000x reference)
#include <cuda_runtime.h>

typedef unsigned long long u64;
#define DI __device__ __forceinline__

DI u64 pack2(float a, float b){ u64 r; asm("mov.b64 %0, {%1,%2};" : "=l"(r) : "f"(a), "f"(b)); return r; }
DI void unpack2(u64 v, float &a, float &b){ asm("mov.b64 {%0,%1}, %2;" : "=f"(a), "=f"(b) : "l"(v)); }
DI u64 fma2(u64 a, u64 b, u64 c){ u64 d; asm("fma.rn.f32x2 %0, %1, %2, %3;" : "=l"(d) : "l"(a), "l"(b), "l"(c)); return d; }

#define NB 2
#define HF 192
#define CC 96
#define EPSC 1e-7f

__device__ float g_a4 [NB*96*96*32];
__device__ float g_a32[NB*24*24*32];
__device__ float g_cat [NB*HF*HF*CC];
__device__ float g_aspp[NB*HF*HF*CC];
__device__ float g_G   [NB*HF*HF*64];

// ---------------- 1x1 conv + bias + relu (feats4 -> a4, feats32 -> a32) -------------
__global__ void k_conv1x1(const float* __restrict__ in, const float* __restrict__ w,
                          const float* __restrict__ bias, int npix, int cin, int which)
{
    extern __shared__ float sm[];
    float* sw  = sm;
    float* spx = sm + cin*32;
    int tx = threadIdx.x, ty = threadIdx.y;
    int tid = ty*32 + tx;
    for (int i = tid; i < cin*32; i += 256) sw[i] = w[i];
    int p = blockIdx.x*8 + ty;
    for (int ci = tx; ci < cin; ci += 32)
        spx[ty*cin + ci] = (p < npix) ? in[p*cin + ci] : 0.f;
    __syncthreads();
    if (p >= npix) return;
    float acc = bias[tx];
    const float* sp = spx + ty*cin;
    #pragma unroll 4
    for (int ci = 0; ci < cin; ci++)
        acc = fmaf(sp[ci], sw[ci*32 + tx], acc);
    float* outp = which ? g_a32 : g_a4;
    outp[p*32 + tx] = fmaxf(acc, 0.f);
}

// ------------- build concat grid : 16 px per block, 512 threads ----
__global__ void __launch_bounds__(512) k_build_cat(const float* __restrict__ feats2,
                            const float* __restrict__ w2, const float* __restrict__ b2)
{
    __shared__ float sw[64*32];
    __shared__ float spx[16][64];
    int tx = threadIdx.x, ty = threadIdx.y;
    int tid = ty*32 + tx;
    for (int i = tid; i < 64*32; i += 512) sw[i] = w2[i];
    int b = blockIdx.z, y = blockIdx.y, x = blockIdx.x*16 + ty;
    int pix = (b*HF + y)*HF + x;
    spx[ty][tx]      = feats2[pix*64 + tx];
    spx[ty][tx + 32] = feats2[pix*64 + tx + 32];
    __syncthreads();

    float* catp = &g_cat[(size_t)pix*CC];
    {
        float acc = b2[tx];
        #pragma unroll 8
        for (int ci = 0; ci < 64; ci++)
            acc = fmaf(spx[ty][ci], sw[ci*32 + tx], acc);
        catp[tx] = fmaxf(acc, 0.f);
    }
    {
        float sy = y*0.5f - 0.25f, sx = x*0.5f - 0.25f;
        int y0 = (int)floorf(sy), x0 = (int)floorf(sx);
        float fy = sy - (float)y0, fx = sx - (float)x0;
        int y0c = max(y0, 0), y1c = min(y0 + 1, 95);
        int x0c = max(x0, 0), x1c = min(x0 + 1, 95);
        const float* base = &g_a4[(size_t)b*96*96*32];
        float v00 = base[(y0c*96 + x0c)*32 + tx];
        float v01 = base[(y0c*96 + x1c)*32 + tx];
        float v10 = base[(y1c*96 + x0c)*32 + tx];
        float v11 = base[(y1c*96 + x1c)*32 + tx];
        float v0 = v00 + fx*(v01 - v00);
        float v1 = v10 + fx*(v11 - v10);
        catp[32 + tx] = v0 + fy*(v1 - v0);
    }
    {
        float sy = y*0.125f - 0.4375f, sx = x*0.125f - 0.4375f;
        int y0 = (int)floorf(sy), x0 = (int)floorf(sx);
        float fy = sy - (float)y0, fx = sx - (float)x0;
        int y0c = max(y0, 0), y1c = min(y0 + 1, 23);
        int x0c = max(x0, 0), x1c = min(x0 + 1, 23);
        const float* base = &g_a32[(size_t)b*24*24*32];
        float v00 = base[(y0c*24 + x0c)*32 + tx];
        float v01 = base[(y0c*24 + x1c)*32 + tx];
        float v10 = base[(y1c*24 + x0c)*32 + tx];
        float v11 = base[(y1c*24 + x1c)*32 + tx];
        float v0 = v00 + fx*(v01 - v00);
        float v1 = v10 + fx*(v11 - v10);
        catp[64 + tx] = v0 + fy*(v1 - v0);
    }
}

// ---------------- 3x3 conv SAME + bias + relu : g_cat -> g_aspp -----------------
// 512 threads: cog=tid&7 (4 co), pxx=(tid>>3)&31, yh=tid>>8 (y half: 3 rows each)
#define CIS 100
#define SINW (8*34*CIS)             // 27200
__global__ void __launch_bounds__(512, 1) k_conv3x3(const float* __restrict__ wf,
                                                    const float* __restrict__ bf)
{
    extern __shared__ float sm[];
    float* s_in = sm;               // 27200
    float* s_w  = sm + SINW;        // 27648
    int tid = threadIdx.x;
    int cog = tid & 7;              // co group of 4
    int pxx = (tid >> 3) & 31;      // 0..31 local x
    int yh  = tid >> 8;             // 0 or 1: y half
    int ybase = yh * 3;
    int xt = blockIdx.x % 6, cs = blockIdx.x / 6;
    int y0 = blockIdx.y * 6, b = blockIdx.z;
    int x0 = xt * 32;

    for (int i = tid; i < 9*96*32; i += 512) {
        int l = i & 31, tci = i >> 5;
        s_w[tci*32 + l] = wf[tci*96 + cs*32 + l];
    }
    for (int i = tid; i < 8*34*24; i += 512) {
        int px = i / 24, c4 = i - px*24;
        int ry = px / 34, xl = px - ry*34;
        int yy = y0 + ry - 1;
        int xx = x0 + xl - 1;
        float4 v = make_float4(0.f, 0.f, 0.f, 0.f);
        if (yy >= 0 && yy < HF && xx >= 0 && xx < HF)
            v = *(const float4*)&g_cat[(((size_t)b*HF + yy)*HF + xx)*CC + c4*4];
        *(float4*)&s_in[px*CIS + c4*4] = v;
    }
    __syncthreads();

    u64 zero = pack2(0.f, 0.f);
    u64 acc[3][2];
    #pragma unroll
    for (int i = 0; i < 3; i++) { acc[i][0] = zero; acc[i][1] = zero; }

    #pragma unroll 4
    for (int ci = 0; ci < 96; ci++) {
        u64 ivb[5][3];
        #pragma unroll
        for (int ry = 0; ry < 5; ry++)
            #pragma unroll
            for (int dx = 0; dx < 3; dx++) {
                float a = s_in[((ybase + ry)*34 + pxx + dx)*CIS + ci];
                ivb[ry][dx] = pack2(a, a);
            }
        const float* wb = &s_w[ci*32 + cog*4];
        #pragma unroll
        for (int t = 0; t < 9; t++) {
            int r = t / 3, dx = t % 3;
            ulonglong2 wA = *(const ulonglong2*)&wb[t*96*32];
            #pragma unroll
            for (int yo = 0; yo < 3; yo++) {
                u64 a = ivb[yo + r][dx];
                acc[yo][0] = fma2(a, wA.x, acc[yo][0]);
                acc[yo][1] = fma2(a, wA.y, acc[yo][1]);
            }
        }
    }

    int co0 = cs*32 + cog*4;
    float bv[4];
    #pragma unroll
    for (int j = 0; j < 4; j++) bv[j] = bf[co0 + j];
    #pragma unroll
    for (int yo = 0; yo < 3; yo++) {
        float o[4];
        #pragma unroll
        for (int j = 0; j < 2; j++) {
            float lo, hi; unpack2(acc[yo][j], lo, hi);
            o[2*j]   = fmaxf(lo + bv[2*j],   0.f);
            o[2*j+1] = fmaxf(hi + bv[2*j+1], 0.f);
        }
        float* op = &g_aspp[(((size_t)b*HF + y0 + ybase + yo)*HF + x0 + pxx)*CC + co0];
        *(float4*)op = make_float4(o[0], o[1], o[2], o[3]);
    }
}

// ---------------- precompute G[px][64] = aspp[px][96] @ W0_feat + b0 -----------------
// 64 px per block, 256 threads; thread = 2 co x 8 px (pairs over px)
#define SAS 66
__global__ void __launch_bounds__(256) k_precg(const float* __restrict__ mw0,
                                               const float* __restrict__ mb0)
{
    __shared__ float sw[96*64];     // [k][co]
    __shared__ float sa[96*SAS];    // [k][px] transposed, stride 66
    int tid = threadIdx.x;
    int p0 = blockIdx.x * 64;

    for (int i = tid; i < 96*64; i += 256) sw[i] = mw0[i];
    for (int i = tid; i < 64*24; i += 256) {
        int px = i / 24, c4 = i - px*24;
        float4 v = *(const float4*)&g_aspp[(size_t)(p0 + px)*96 + c4*4];
        sa[(c4*4 + 0)*SAS + px] = v.x;
        sa[(c4*4 + 1)*SAS + px] = v.y;
        sa[(c4*4 + 2)*SAS + px] = v.z;
        sa[(c4*4 + 3)*SAS + px] = v.w;
    }
    __syncthreads();

    int cop = tid & 31;             // co pair: co = cop*2
    int pxg = tid >> 5;             // px base = pxg*8
    u64 zero = pack2(0.f, 0.f);
    u64 acc0[4] = {zero, zero, zero, zero};
    u64 acc1[4] = {zero, zero, zero, zero};

    #pragma unroll 4
    for (int k = 0; k < 96; k++) {
        float2 w = *(const float2*)&sw[k*64 + cop*2];
        u64 w0 = pack2(w.x, w.x), w1 = pack2(w.y, w.y);
        const u64* ap = (const u64*)&sa[k*SAS + pxg*8];
        #pragma unroll
        for (int j = 0; j < 4; j++) {
            u64 a = ap[j];
            acc0[j] = fma2(a, w0, acc0[j]);
            acc1[j] = fma2(a, w1, acc1[j]);
        }
    }

    float b0v = mb0[cop*2], b1v = mb0[cop*2 + 1];
    #pragma unroll
    for (int j = 0; j < 4; j++) {
        float a_lo, a_hi, b_lo, b_hi;
        unpack2(acc0[j], a_lo, a_hi);
        unpack2(acc1[j], b_lo, b_hi);
        int px = p0 + pxg*8 + 2*j;
        *(float2*)&g_G[(size_t)px*64 + cop*2]       = make_float2(a_lo + b0v, b_lo + b1v);
        *(float2*)&g_G[(size_t)(px + 1)*64 + cop*2] = make_float2(a_hi + b0v, b_hi + b1v);
    }
}

// ---------------- fused gather + tiny-MLP + area combine -----------------
#define HS 65
#define QPB 64
#define ROWS 256
__global__ void __launch_bounds__(256, 2) k_mlp(
    const float* __restrict__ coords, const float* __restrict__ cells,
    const float* __restrict__ mw0, const float* __restrict__ mb0,
    const float* __restrict__ mw1, const float* __restrict__ mb1,
    const float* __restrict__ mw2, const float* __restrict__ mb2,
    float* __restrict__ out)
{
    extern __shared__ float sm[];
    float* s_w0s  = sm;                    // 384
    float* s_w1   = s_w0s + 384;           // 4096
    float* s_b1   = s_w1 + 4096;           // 64
    float* s_w2   = s_b1 + 64;             // 64
    float* s_sc   = s_w2 + 64;             // 256*8 scalars
    float* s_area = s_sc + ROWS*8;         // 256
    float* s_h    = s_area + ROWS;         // 256*65
    float* s_part = s_h + ROWS*HS;         // 256*8
    float* s_pred = s_part + ROWS*8;       // 256
    int*   s_pix  = (int*)(s_pred + ROWS); // 256

    int tid = threadIdx.x;
    for (int i = tid; i < 384; i += 256) s_w0s[i] = mw0[96*64 + i];
    for (int i = tid; i < 4096; i += 256) s_w1[i] = mw1[i];
    if (tid < 64) { s_b1[tid] = mb1[tid]; s_w2[tid] = mw2[tid]; }

    int q0 = blockIdx.x * QPB;

    // ---- Phase A ----
    {
        int r = tid;
        int q = q0 + (r >> 2), c = r & 3;
        int bq = q / (384*384);
        float cy = coords[q*2], cx = coords[q*2 + 1];
        float vy = (c & 2) ? 1.f : -1.f;
        float vx = (c & 1) ? 1.f : -1.f;
        const float RX = 1.0f/192.0f;
        float fy = __fadd_rn(__fadd_rn(cy, __fmul_rn(vy, RX)), EPSC);
        float fx = __fadd_rn(__fadd_rn(cx, __fmul_rn(vx, RX)), EPSC);
        fy = fminf(fmaxf(fy, -1.f + EPSC), 1.f - EPSC);
        fx = fminf(fmaxf(fx, -1.f + EPSC), 1.f - EPSC);
        float tyf = __fadd_rn(__fmul_rn(__fmul_rn(__fadd_rn(fy, 1.f), 192.f), 0.5f), -0.5f);
        float txf = __fadd_rn(__fmul_rn(__fmul_rn(__fadd_rn(fx, 1.f), 192.f), 0.5f), -0.5f);
        int iy = min(max((int)rintf(tyf), 0), 191);
        int ix = min(max((int)rintf(txf), 0), 191);

        s_pix[r] = (bq*HF + iy)*HF + ix;

        float csy = __fadd_rn(__fmul_rn(__fdiv_rn(__fadd_rn((float)iy, 0.5f), 192.f), 2.f), -1.f);
        float csx = __fadd_rn(__fmul_rn(__fdiv_rn(__fadd_rn((float)ix, 0.5f), 192.f), 2.f), -1.f);
        float ry = __fmul_rn(__fsub_rn(cy, csy), 192.f);
        float rx = __fmul_rn(__fsub_rn(cx, csx), 192.f);
        float rcy = __fmul_rn(cells[q*2],     192.f);
        float rcx = __fmul_rn(cells[q*2 + 1], 192.f);
        float* sc = &s_sc[r*8];
        sc[0] = ry; sc[1] = rx; sc[2] = cy; sc[3] = cx; sc[4] = rcy; sc[5] = rcx;
        s_area[r] = fabsf(__fmul_rn(ry, rx)) + EPSC;
    }
    __syncthreads();

    int tx8 = tid & 7, tyr = tid >> 3;
    int R0 = tyr * 8;
    u64 zero = pack2(0.f, 0.f);

    // ---- Layer 1: h = relu(G[pix] + scal(6) @ W0s) ----
    {
        u64 acc[8][4];
        #pragma unroll
        for (int i = 0; i < 8; i++) {
            const u64* gp = (const u64*)&g_G[(size_t)s_pix[R0 + i]*64 + tx8*8];
            #pragma unroll
            for (int j = 0; j < 4; j++) acc[i][j] = gp[j];
        }
        #pragma unroll
        for (int s = 0; s < 6; s++) {
            const ulonglong2* wp = (const ulonglong2*)&s_w0s[s*64 + tx8*8];
            ulonglong2 w01 = wp[0], w23 = wp[1];
            #pragma unroll
            for (int i = 0; i < 8; i++) {
                float a = s_sc[(R0 + i)*8 + s];
                u64 ap = pack2(a, a);
                acc[i][0] = fma2(ap, w01.x, acc[i][0]);
                acc[i][1] = fma2(ap, w01.y, acc[i][1]);
                acc[i][2] = fma2(ap, w23.x, acc[i][2]);
                acc[i][3] = fma2(ap, w23.y, acc[i][3]);
            }
        }
        #pragma unroll
        for (int i = 0; i < 8; i++) {
            int row = R0 + i;
            #pragma unroll
            for (int j = 0; j < 4; j++) {
                float lo, hi; unpack2(acc[i][j], lo, hi);
                int c = tx8*8 + 2*j;
                s_h[row*HS + c]     = fmaxf(lo, 0.f);
                s_h[row*HS + c + 1] = fmaxf(hi, 0.f);
            }
        }
    }
    __syncthreads();

    // ---- Layer 2 + fold with w2 ----
    {
        u64 acc[8][4];
        #pragma unroll
        for (int i = 0; i < 8; i++)
            #pragma unroll
            for (int j = 0; j < 4; j++) acc[i][j] = zero;
        const float* hb = &s_h[R0*HS];
        #pragma unroll 4
        for (int k = 0; k < 64; k++) {
            const ulonglong2* wp = (const ulonglong2*)&s_w1[k*64 + tx8*8];
            ulonglong2 w01 = wp[0], w23 = wp[1];
            #pragma unroll
            for (int i = 0; i < 8; i++) {
                float a = hb[i*HS + k];
                u64 ap = pack2(a, a);
                acc[i][0] = fma2(ap, w01.x, acc[i][0]);
                acc[i][1] = fma2(ap, w01.y, acc[i][1]);
                acc[i][2] = fma2(ap, w23.x, acc[i][2]);
                acc[i][3] = fma2(ap, w23.y, acc[i][3]);
            }
        }
        #pragma unroll
        for (int i = 0; i < 8; i++) {
            int row = R0 + i;
            float part = 0.f;
            #pragma unroll
            for (int j = 0; j < 4; j++) {
                float lo, hi; unpack2(acc[i][j], lo, hi);
                int c = tx8*8 + 2*j;
                part = fmaf(fmaxf(lo + s_b1[c],     0.f), s_w2[c],     part);
                part = fmaf(fmaxf(hi + s_b1[c + 1], 0.f), s_w2[c + 1], part);
            }
            s_part[row*8 + tx8] = part;
        }
    }
    __syncthreads();

    {
        float p = mb2[0];
        #pragma unroll
        for (int j = 0; j < 8; j++) p += s_part[tid*8 + j];
        s_pred[tid] = p;
    }
    __syncthreads();

    if (tid < QPB) {
        int r = tid*4;
        float a0 = s_area[r], a1 = s_area[r+1], a2 = s_area[r+2], a3 = s_area[r+3];
        float p0 = s_pred[r], p1 = s_pred[r+1], p2 = s_pred[r+2], p3 = s_pred[r+3];
        float num = p0*a3 + p1*a2 + p2*a1 + p3*a0;
        float den = a3 + a2 + a1 + a0;
        out[q0 + tid] = num / den;
    }
}

extern "C" void kernel_launch(void* const* d_in, const int* in_sizes, int n_in,
                              void* d_out, int out_size)
{
    const float* feats2 = (const float*)d_in[0];
    const float* feats4 = (const float*)d_in[1];
    const float* feats32= (const float*)d_in[2];
    const float* coords = (const float*)d_in[3];
    const float* cells  = (const float*)d_in[4];
    const float* w2  = (const float*)d_in[5];
    const float* b2  = (const float*)d_in[6];
    const float* w4  = (const float*)d_in[7];
    const float* b4  = (const float*)d_in[8];
    const float* w32 = (const float*)d_in[9];
    const float* b32 = (const float*)d_in[10];
    const float* wf  = (const float*)d_in[11];
    const float* bf  = (const float*)d_in[12];
    const float* mw0 = (const float*)d_in[13];
    const float* mb0 = (const float*)d_in[14];
    const float* mw1 = (const float*)d_in[15];
    const float* mb1 = (const float*)d_in[16];
    const float* mw2 = (const float*)d_in[17];
    const float* mb2 = (const float*)d_in[18];
    float* out = (float*)d_out;

    dim3 blk(32, 8);

    k_conv1x1<<<NB*96*96/8, blk, (96*32 + 8*96)*sizeof(float)>>>(feats4, w4, b4, NB*96*96, 96, 0);
    k_conv1x1<<<NB*24*24/8, blk, (160*32 + 8*160)*sizeof(float)>>>(feats32, w32, b32, NB*24*24, 160, 1);

    k_build_cat<<<dim3(HF/16, HF, NB), dim3(32, 16)>>>(feats2, w2, b2);

    // 3x3 conv: 6y x 32x px tile, 32-co set, 512 threads (3y x 4co per thread)
    size_t smem3 = (size_t)(SINW + 9*96*32) * sizeof(float);   // 219392 B
    cudaFuncSetAttribute(k_conv3x3, cudaFuncAttributeMaxDynamicSharedMemorySize, (int)smem3);
    k_conv3x3<<<dim3(6*3, 32, NB), 512, smem3>>>(wf, bf);

    // precompute G = aspp @ W0_feat + b0 : 64 px/block
    k_precg<<<NB*HF*HF/64, 256>>>(mw0, mb0);

    // fused gather + tiny MLP: 64 queries/block, 256 threads, 2 CTAs/SM
    size_t smemM = (size_t)(384 + 4096 + 64 + 64 + ROWS*8 + ROWS + ROWS*HS + ROWS*8 + ROWS + ROWS) * sizeof(float);
    cudaFuncSetAttribute(k_mlp, cudaFuncAttributeMaxDynamicSharedMemorySize, (int)smemM);
    k_mlp<<<(NB*384*384)/QPB, 256, smemM>>>(coords, cells, mw0, mb0, mw1, mb1, mw2, mb2, out);
}

// round 10
// speedup vs baseline: 1.0677x; 1.0677x over previous
#include <cuda_runtime.h>

typedef unsigned long long u64;
#define DI __device__ __forceinline__

DI u64 pack2(float a, float b){ u64 r; asm("mov.b64 %0, {%1,%2};" : "=l"(r) : "f"(a), "f"(b)); return r; }
DI void unpack2(u64 v, float &a, float &b){ asm("mov.b64 {%0,%1}, %2;" : "=f"(a), "=f"(b) : "l"(v)); }
DI u64 fma2(u64 a, u64 b, u64 c){ u64 d; asm("fma.rn.f32x2 %0, %1, %2, %3;" : "=l"(d) : "l"(a), "l"(b), "l"(c)); return d; }

#define NB 2
#define HF 192
#define CC 96
#define EPSC 1e-7f

__device__ float g_a4 [NB*96*96*32];
__device__ float g_a32[NB*24*24*32];
__device__ float g_cat [NB*HF*HF*CC];
__device__ float g_aspp[NB*HF*HF*CC];
__device__ float g_G   [NB*HF*HF*64];

// ---------------- 1x1 conv + bias + relu (feats4 -> a4, feats32 -> a32) -------------
__global__ void k_conv1x1(const float* __restrict__ in, const float* __restrict__ w,
                          const float* __restrict__ bias, int npix, int cin, int which)
{
    extern __shared__ float sm[];
    float* sw  = sm;
    float* spx = sm + cin*32;
    int tx = threadIdx.x, ty = threadIdx.y;
    int tid = ty*32 + tx;
    for (int i = tid; i < cin*32; i += 256) sw[i] = w[i];
    int p = blockIdx.x*8 + ty;
    for (int ci = tx; ci < cin; ci += 32)
        spx[ty*cin + ci] = (p < npix) ? in[p*cin + ci] : 0.f;
    __syncthreads();
    if (p >= npix) return;
    float acc = bias[tx];
    const float* sp = spx + ty*cin;
    #pragma unroll 4
    for (int ci = 0; ci < cin; ci++)
        acc = fmaf(sp[ci], sw[ci*32 + tx], acc);
    float* outp = which ? g_a32 : g_a4;
    outp[p*32 + tx] = fmaxf(acc, 0.f);
}

// ------------- build concat grid : 16 px per block, 512 threads ----
__global__ void __launch_bounds__(512) k_build_cat(const float* __restrict__ feats2,
                            const float* __restrict__ w2, const float* __restrict__ b2)
{
    __shared__ float sw[64*32];
    __shared__ float spx[16][64];
    int tx = threadIdx.x, ty = threadIdx.y;
    int tid = ty*32 + tx;
    for (int i = tid; i < 64*32; i += 512) sw[i] = w2[i];
    int b = blockIdx.z, y = blockIdx.y, x = blockIdx.x*16 + ty;
    int pix = (b*HF + y)*HF + x;
    spx[ty][tx]      = feats2[pix*64 + tx];
    spx[ty][tx + 32] = feats2[pix*64 + tx + 32];
    __syncthreads();

    float* catp = &g_cat[(size_t)pix*CC];
    {
        float acc = b2[tx];
        #pragma unroll 8
        for (int ci = 0; ci < 64; ci++)
            acc = fmaf(spx[ty][ci], sw[ci*32 + tx], acc);
        catp[tx] = fmaxf(acc, 0.f);
    }
    {
        float sy = y*0.5f - 0.25f, sx = x*0.5f - 0.25f;
        int y0 = (int)floorf(sy), x0 = (int)floorf(sx);
        float fy = sy - (float)y0, fx = sx - (float)x0;
        int y0c = max(y0, 0), y1c = min(y0 + 1, 95);
        int x0c = max(x0, 0), x1c = min(x0 + 1, 95);
        const float* base = &g_a4[(size_t)b*96*96*32];
        float v00 = base[(y0c*96 + x0c)*32 + tx];
        float v01 = base[(y0c*96 + x1c)*32 + tx];
        float v10 = base[(y1c*96 + x0c)*32 + tx];
        float v11 = base[(y1c*96 + x1c)*32 + tx];
        float v0 = v00 + fx*(v01 - v00);
        float v1 = v10 + fx*(v11 - v10);
        catp[32 + tx] = v0 + fy*(v1 - v0);
    }
    {
        float sy = y*0.125f - 0.4375f, sx = x*0.125f - 0.4375f;
        int y0 = (int)floorf(sy), x0 = (int)floorf(sx);
        float fy = sy - (float)y0, fx = sx - (float)x0;
        int y0c = max(y0, 0), y1c = min(y0 + 1, 23);
        int x0c = max(x0, 0), x1c = min(x0 + 1, 23);
        const float* base = &g_a32[(size_t)b*24*24*32];
        float v00 = base[(y0c*24 + x0c)*32 + tx];
        float v01 = base[(y0c*24 + x1c)*32 + tx];
        float v10 = base[(y1c*24 + x0c)*32 + tx];
        float v11 = base[(y1c*24 + x1c)*32 + tx];
        float v0 = v00 + fx*(v01 - v00);
        float v1 = v10 + fx*(v11 - v10);
        catp[64 + tx] = v0 + fy*(v1 - v0);
    }
}

// ---------------- 3x3 conv SAME + bias + relu : g_cat -> g_aspp -----------------
// R8 shape: 256 threads: cog=tid&7 (4 co), pxx=tid>>3 (32 x), 6y per thread, unroll 4
#define CIS 100
#define SINW (8*34*CIS)             // 27200
__global__ void __launch_bounds__(256, 1) k_conv3x3(const float* __restrict__ wf,
                                                    const float* __restrict__ bf)
{
    extern __shared__ float sm[];
    float* s_in = sm;               // 27200
    float* s_w  = sm + SINW;        // 27648
    int tid = threadIdx.x;
    int cog = tid & 7;              // co group of 4
    int pxx = tid >> 3;             // 0..31 local x
    int xt = blockIdx.x % 6, cs = blockIdx.x / 6;
    int y0 = blockIdx.y * 6, b = blockIdx.z;
    int x0 = xt * 32;

    for (int i = tid; i < 9*96*32; i += 256) {
        int l = i & 31, tci = i >> 5;
        s_w[tci*32 + l] = wf[tci*96 + cs*32 + l];
    }
    for (int i = tid; i < 8*34*24; i += 256) {
        int px = i / 24, c4 = i - px*24;
        int ry = px / 34, xl = px - ry*34;
        int yy = y0 + ry - 1;
        int xx = x0 + xl - 1;
        float4 v = make_float4(0.f, 0.f, 0.f, 0.f);
        if (yy >= 0 && yy < HF && xx >= 0 && xx < HF)
            v = *(const float4*)&g_cat[(((size_t)b*HF + yy)*HF + xx)*CC + c4*4];
        *(float4*)&s_in[px*CIS + c4*4] = v;
    }
    __syncthreads();

    u64 zero = pack2(0.f, 0.f);
    u64 acc[6][2];
    #pragma unroll
    for (int i = 0; i < 6; i++) { acc[i][0] = zero; acc[i][1] = zero; }

    #pragma unroll 4
    for (int ci = 0; ci < 96; ci++) {
        u64 ivb[8][3];
        #pragma unroll
        for (int ry = 0; ry < 8; ry++)
            #pragma unroll
            for (int dx = 0; dx < 3; dx++) {
                float a = s_in[(ry*34 + pxx + dx)*CIS + ci];
                ivb[ry][dx] = pack2(a, a);
            }
        const float* wb = &s_w[ci*32 + cog*4];
        #pragma unroll
        for (int t = 0; t < 9; t++) {
            int r = t / 3, dx = t % 3;
            ulonglong2 wA = *(const ulonglong2*)&wb[t*96*32];
            #pragma unroll
            for (int yo = 0; yo < 6; yo++) {
                u64 a = ivb[yo + r][dx];
                acc[yo][0] = fma2(a, wA.x, acc[yo][0]);
                acc[yo][1] = fma2(a, wA.y, acc[yo][1]);
            }
        }
    }

    int co0 = cs*32 + cog*4;
    float bv[4];
    #pragma unroll
    for (int j = 0; j < 4; j++) bv[j] = bf[co0 + j];
    #pragma unroll
    for (int yo = 0; yo < 6; yo++) {
        float o[4];
        #pragma unroll
        for (int j = 0; j < 2; j++) {
            float lo, hi; unpack2(acc[yo][j], lo, hi);
            o[2*j]   = fmaxf(lo + bv[2*j],   0.f);
            o[2*j+1] = fmaxf(hi + bv[2*j+1], 0.f);
        }
        float* op = &g_aspp[(((size_t)b*HF + y0 + yo)*HF + x0 + pxx)*CC + co0];
        *(float4*)op = make_float4(o[0], o[1], o[2], o[3]);
    }
}

// ---------------- precompute G[px][64] = aspp[px][96] @ W0_feat + b0 -----------------
// 128 px per block, 512 threads; thread = 2 co x 8 px (pairs over px)
#define SAS 130
__global__ void __launch_bounds__(512) k_precg(const float* __restrict__ mw0,
                                               const float* __restrict__ mb0)
{
    __shared__ float sw[96*64];     // [k][co]
    __shared__ float sa[96*SAS];    // [k][px] transposed, stride 130
    int tid = threadIdx.x;
    int p0 = blockIdx.x * 128;

    for (int i = tid; i < 96*64; i += 512) sw[i] = mw0[i];
    for (int i = tid; i < 128*24; i += 512) {
        int px = i / 24, c4 = i - px*24;
        float4 v = *(const float4*)&g_aspp[(size_t)(p0 + px)*96 + c4*4];
        sa[(c4*4 + 0)*SAS + px] = v.x;
        sa[(c4*4 + 1)*SAS + px] = v.y;
        sa[(c4*4 + 2)*SAS + px] = v.z;
        sa[(c4*4 + 3)*SAS + px] = v.w;
    }
    __syncthreads();

    int cop = tid & 31;             // co pair: co = cop*2
    int pxg = tid >> 5;             // px base = pxg*8 (0..15)
    u64 zero = pack2(0.f, 0.f);
    u64 acc0[4] = {zero, zero, zero, zero};
    u64 acc1[4] = {zero, zero, zero, zero};

    #pragma unroll 4
    for (int k = 0; k < 96; k++) {
        float2 w = *(const float2*)&sw[k*64 + cop*2];
        u64 w0 = pack2(w.x, w.x), w1 = pack2(w.y, w.y);
        const u64* ap = (const u64*)&sa[k*SAS + pxg*8];
        #pragma unroll
        for (int j = 0; j < 4; j++) {
            u64 a = ap[j];
            acc0[j] = fma2(a, w0, acc0[j]);
            acc1[j] = fma2(a, w1, acc1[j]);
        }
    }

    float b0v = mb0[cop*2], b1v = mb0[cop*2 + 1];
    #pragma unroll
    for (int j = 0; j < 4; j++) {
        float a_lo, a_hi, b_lo, b_hi;
        unpack2(acc0[j], a_lo, a_hi);
        unpack2(acc1[j], b_lo, b_hi);
        int px = p0 + pxg*8 + 2*j;
        *(float2*)&g_G[(size_t)px*64 + cop*2]       = make_float2(a_lo + b0v, b_lo + b1v);
        *(float2*)&g_G[(size_t)(px + 1)*64 + cop*2] = make_float2(a_hi + b0v, b_hi + b1v);
    }
}

// ---------------- fused gather + tiny-MLP + area combine -----------------
#define HS 65
#define QPB 64
#define ROWS 256
__global__ void __launch_bounds__(256, 2) k_mlp(
    const float* __restrict__ coords, const float* __restrict__ cells,
    const float* __restrict__ mw0, const float* __restrict__ mb0,
    const float* __restrict__ mw1, const float* __restrict__ mb1,
    const float* __restrict__ mw2, const float* __restrict__ mb2,
    float* __restrict__ out)
{
    extern __shared__ float sm[];
    float* s_w0s  = sm;                    // 384
    float* s_w1   = s_w0s + 384;           // 4096
    float* s_b1   = s_w1 + 4096;           // 64
    float* s_w2   = s_b1 + 64;             // 64
    float* s_sc   = s_w2 + 64;             // 256*8 scalars
    float* s_area = s_sc + ROWS*8;         // 256
    float* s_h    = s_area + ROWS;         // 256*65
    float* s_part = s_h + ROWS*HS;         // 256*8
    float* s_pred = s_part + ROWS*8;       // 256
    int*   s_pix  = (int*)(s_pred + ROWS); // 256

    int tid = threadIdx.x;
    for (int i = tid; i < 384; i += 256) s_w0s[i] = mw0[96*64 + i];
    for (int i = tid; i < 4096; i += 256) s_w1[i] = mw1[i];
    if (tid < 64) { s_b1[tid] = mb1[tid]; s_w2[tid] = mw2[tid]; }

    int q0 = blockIdx.x * QPB;

    // ---- Phase A ----
    {
        int r = tid;
        int q = q0 + (r >> 2), c = r & 3;
        int bq = q / (384*384);
        float cy = coords[q*2], cx = coords[q*2 + 1];
        float vy = (c & 2) ? 1.f : -1.f;
        float vx = (c & 1) ? 1.f : -1.f;
        const float RX = 1.0f/192.0f;
        float fy = __fadd_rn(__fadd_rn(cy, __fmul_rn(vy, RX)), EPSC);
        float fx = __fadd_rn(__fadd_rn(cx, __fmul_rn(vx, RX)), EPSC);
        fy = fminf(fmaxf(fy, -1.f + EPSC), 1.f - EPSC);
        fx = fminf(fmaxf(fx, -1.f + EPSC), 1.f - EPSC);
        float tyf = __fadd_rn(__fmul_rn(__fmul_rn(__fadd_rn(fy, 1.f), 192.f), 0.5f), -0.5f);
        float txf = __fadd_rn(__fmul_rn(__fmul_rn(__fadd_rn(fx, 1.f), 192.f), 0.5f), -0.5f);
        int iy = min(max((int)rintf(tyf), 0), 191);
        int ix = min(max((int)rintf(txf), 0), 191);

        s_pix[r] = (bq*HF + iy)*HF + ix;

        float csy = __fadd_rn(__fmul_rn(__fdiv_rn(__fadd_rn((float)iy, 0.5f), 192.f), 2.f), -1.f);
        float csx = __fadd_rn(__fmul_rn(__fdiv_rn(__fadd_rn((float)ix, 0.5f), 192.f), 2.f), -1.f);
        float ry = __fmul_rn(__fsub_rn(cy, csy), 192.f);
        float rx = __fmul_rn(__fsub_rn(cx, csx), 192.f);
        float rcy = __fmul_rn(cells[q*2],     192.f);
        float rcx = __fmul_rn(cells[q*2 + 1], 192.f);
        float* sc = &s_sc[r*8];
        sc[0] = ry; sc[1] = rx; sc[2] = cy; sc[3] = cx; sc[4] = rcy; sc[5] = rcx;
        s_area[r] = fabsf(__fmul_rn(ry, rx)) + EPSC;
    }
    __syncthreads();

    int tx8 = tid & 7, tyr = tid >> 3;
    int R0 = tyr * 8;
    u64 zero = pack2(0.f, 0.f);

    // ---- Layer 1: h = relu(G[pix] + scal(6) @ W0s) ----
    {
        u64 acc[8][4];
        #pragma unroll
        for (int i = 0; i < 8; i++) {
            const u64* gp = (const u64*)&g_G[(size_t)s_pix[R0 + i]*64 + tx8*8];
            #pragma unroll
            for (int j = 0; j < 4; j++) acc[i][j] = gp[j];
        }
        #pragma unroll
        for (int s = 0; s < 6; s++) {
            const ulonglong2* wp = (const ulonglong2*)&s_w0s[s*64 + tx8*8];
            ulonglong2 w01 = wp[0], w23 = wp[1];
            #pragma unroll
            for (int i = 0; i < 8; i++) {
                float a = s_sc[(R0 + i)*8 + s];
                u64 ap = pack2(a, a);
                acc[i][0] = fma2(ap, w01.x, acc[i][0]);
                acc[i][1] = fma2(ap, w01.y, acc[i][1]);
                acc[i][2] = fma2(ap, w23.x, acc[i][2]);
                acc[i][3] = fma2(ap, w23.y, acc[i][3]);
            }
        }
        #pragma unroll
        for (int i = 0; i < 8; i++) {
            int row = R0 + i;
            #pragma unroll
            for (int j = 0; j < 4; j++) {
                float lo, hi; unpack2(acc[i][j], lo, hi);
                int c = tx8*8 + 2*j;
                s_h[row*HS + c]     = fmaxf(lo, 0.f);
                s_h[row*HS + c + 1] = fmaxf(hi, 0.f);
            }
        }
    }
    __syncthreads();

    // ---- Layer 2 + fold with w2 ----
    {
        u64 acc[8][4];
        #pragma unroll
        for (int i = 0; i < 8; i++)
            #pragma unroll
            for (int j = 0; j < 4; j++) acc[i][j] = zero;
        const float* hb = &s_h[R0*HS];
        #pragma unroll 8
        for (int k = 0; k < 64; k++) {
            const ulonglong2* wp = (const ulonglong2*)&s_w1[k*64 + tx8*8];
            ulonglong2 w01 = wp[0], w23 = wp[1];
            #pragma unroll
            for (int i = 0; i < 8; i++) {
                float a = hb[i*HS + k];
                u64 ap = pack2(a, a);
                acc[i][0] = fma2(ap, w01.x, acc[i][0]);
                acc[i][1] = fma2(ap, w01.y, acc[i][1]);
                acc[i][2] = fma2(ap, w23.x, acc[i][2]);
                acc[i][3] = fma2(ap, w23.y, acc[i][3]);
            }
        }
        #pragma unroll
        for (int i = 0; i < 8; i++) {
            int row = R0 + i;
            float part = 0.f;
            #pragma unroll
            for (int j = 0; j < 4; j++) {
                float lo, hi; unpack2(acc[i][j], lo, hi);
                int c = tx8*8 + 2*j;
                part = fmaf(fmaxf(lo + s_b1[c],     0.f), s_w2[c],     part);
                part = fmaf(fmaxf(hi + s_b1[c + 1], 0.f), s_w2[c + 1], part);
            }
            s_part[row*8 + tx8] = part;
        }
    }
    __syncthreads();

    {
        float p = mb2[0];
        #pragma unroll
        for (int j = 0; j < 8; j++) p += s_part[tid*8 + j];
        s_pred[tid] = p;
    }
    __syncthreads();

    if (tid < QPB) {
        int r = tid*4;
        float a0 = s_area[r], a1 = s_area[r+1], a2 = s_area[r+2], a3 = s_area[r+3];
        float p0 = s_pred[r], p1 = s_pred[r+1], p2 = s_pred[r+2], p3 = s_pred[r+3];
        float num = p0*a3 + p1*a2 + p2*a1 + p3*a0;
        float den = a3 + a2 + a1 + a0;
        out[q0 + tid] = num / den;
    }
}

extern "C" void kernel_launch(void* const* d_in, const int* in_sizes, int n_in,
                              void* d_out, int out_size)
{
    const float* feats2 = (const float*)d_in[0];
    const float* feats4 = (const float*)d_in[1];
    const float* feats32= (const float*)d_in[2];
    const float* coords = (const float*)d_in[3];
    const float* cells  = (const float*)d_in[4];
    const float* w2  = (const float*)d_in[5];
    const float* b2  = (const float*)d_in[6];
    const float* w4  = (const float*)d_in[7];
    const float* b4  = (const float*)d_in[8];
    const float* w32 = (const float*)d_in[9];
    const float* b32 = (const float*)d_in[10];
    const float* wf  = (const float*)d_in[11];
    const float* bf  = (const float*)d_in[12];
    const float* mw0 = (const float*)d_in[13];
    const float* mb0 = (const float*)d_in[14];
    const float* mw1 = (const float*)d_in[15];
    const float* mb1 = (const float*)d_in[16];
    const float* mw2 = (const float*)d_in[17];
    const float* mb2 = (const float*)d_in[18];
    float* out = (float*)d_out;

    dim3 blk(32, 8);

    k_conv1x1<<<NB*96*96/8, blk, (96*32 + 8*96)*sizeof(float)>>>(feats4, w4, b4, NB*96*96, 96, 0);
    k_conv1x1<<<NB*24*24/8, blk, (160*32 + 8*160)*sizeof(float)>>>(feats32, w32, b32, NB*24*24, 160, 1);

    k_build_cat<<<dim3(HF/16, HF, NB), dim3(32, 16)>>>(feats2, w2, b2);

    // 3x3 conv: 6y x 32x px tile, 32-co set, 256 threads (R8 config)
    size_t smem3 = (size_t)(SINW + 9*96*32) * sizeof(float);   // 219392 B
    cudaFuncSetAttribute(k_conv3x3, cudaFuncAttributeMaxDynamicSharedMemorySize, (int)smem3);
    k_conv3x3<<<dim3(6*3, 32, NB), 256, smem3>>>(wf, bf);

    // precompute G = aspp @ W0_feat + b0 : 128 px/block, 512 threads
    size_t smemP = (size_t)(96*64 + 96*SAS) * sizeof(float);   // 74496 B
    cudaFuncSetAttribute(k_precg, cudaFuncAttributeMaxDynamicSharedMemorySize, (int)smemP);
    k_precg<<<NB*HF*HF/128, 512, smemP>>>(mw0, mb0);

    // fused gather + tiny MLP: 64 queries/block, 256 threads, 2 CTAs/SM
    size_t smemM = (size_t)(384 + 4096 + 64 + 64 + ROWS*8 + ROWS + ROWS*HS + ROWS*8 + ROWS + ROWS) * sizeof(float);
    cudaFuncSetAttribute(k_mlp, cudaFuncAttributeMaxDynamicSharedMemorySize, (int)smemM);
    k_mlp<<<(NB*384*384)/QPB, 256, smemM>>>(coords, cells, mw0, mb0, mw1, mb1, mw2, mb2, out);
}

// round 11
// speedup vs baseline: 1.1145x; 1.0439x over previous
#include <cuda_runtime.h>

typedef unsigned long long u64;
#define DI __device__ __forceinline__

DI u64 pack2(float a, float b){ u64 r; asm("mov.b64 %0, {%1,%2};" : "=l"(r) : "f"(a), "f"(b)); return r; }
DI void unpack2(u64 v, float &a, float &b){ asm("mov.b64 {%0,%1}, %2;" : "=f"(a), "=f"(b) : "l"(v)); }
DI u64 fma2(u64 a, u64 b, u64 c){ u64 d; asm("fma.rn.f32x2 %0, %1, %2, %3;" : "=l"(d) : "l"(a), "l"(b), "l"(c)); return d; }

#define NB 2
#define HF 192
#define CC 96
#define EPSC 1e-7f

__device__ float g_a4 [NB*96*96*32];
__device__ float g_a32[NB*24*24*32];
__device__ float g_cat [NB*HF*HF*CC];
__device__ float g_aspp[NB*HF*HF*CC];
__device__ float g_G   [NB*HF*HF*64];

// ---------------- 1x1 conv + bias + relu (feats4 -> a4, feats32 -> a32) -------------
__global__ void k_conv1x1(const float* __restrict__ in, const float* __restrict__ w,
                          const float* __restrict__ bias, int npix, int cin, int which)
{
    extern __shared__ float sm[];
    float* sw  = sm;
    float* spx = sm + cin*32;
    int tx = threadIdx.x, ty = threadIdx.y;
    int tid = ty*32 + tx;
    for (int i = tid; i < cin*32; i += 256) sw[i] = w[i];
    int p = blockIdx.x*8 + ty;
    for (int ci = tx; ci < cin; ci += 32)
        spx[ty*cin + ci] = (p < npix) ? in[p*cin + ci] : 0.f;
    __syncthreads();
    if (p >= npix) return;
    float acc = bias[tx];
    const float* sp = spx + ty*cin;
    #pragma unroll 4
    for (int ci = 0; ci < cin; ci++)
        acc = fmaf(sp[ci], sw[ci*32 + tx], acc);
    float* outp = which ? g_a32 : g_a4;
    outp[p*32 + tx] = fmaxf(acc, 0.f);
}

// ------------- build concat grid : 16 px per block, 512 threads ----
__global__ void __launch_bounds__(512) k_build_cat(const float* __restrict__ feats2,
                            const float* __restrict__ w2, const float* __restrict__ b2)
{
    __shared__ float sw[64*32];
    __shared__ float spx[16][64];
    int tx = threadIdx.x, ty = threadIdx.y;
    int tid = ty*32 + tx;
    for (int i = tid; i < 64*32; i += 512) sw[i] = w2[i];
    int b = blockIdx.z, y = blockIdx.y, x = blockIdx.x*16 + ty;
    int pix = (b*HF + y)*HF + x;
    spx[ty][tx]      = feats2[pix*64 + tx];
    spx[ty][tx + 32] = feats2[pix*64 + tx + 32];
    __syncthreads();

    float* catp = &g_cat[(size_t)pix*CC];
    {
        float acc = b2[tx];
        #pragma unroll 8
        for (int ci = 0; ci < 64; ci++)
            acc = fmaf(spx[ty][ci], sw[ci*32 + tx], acc);
        catp[tx] = fmaxf(acc, 0.f);
    }
    {
        float sy = y*0.5f - 0.25f, sx = x*0.5f - 0.25f;
        int y0 = (int)floorf(sy), x0 = (int)floorf(sx);
        float fy = sy - (float)y0, fx = sx - (float)x0;
        int y0c = max(y0, 0), y1c = min(y0 + 1, 95);
        int x0c = max(x0, 0), x1c = min(x0 + 1, 95);
        const float* base = &g_a4[(size_t)b*96*96*32];
        float v00 = base[(y0c*96 + x0c)*32 + tx];
        float v01 = base[(y0c*96 + x1c)*32 + tx];
        float v10 = base[(y1c*96 + x0c)*32 + tx];
        float v11 = base[(y1c*96 + x1c)*32 + tx];
        float v0 = v00 + fx*(v01 - v00);
        float v1 = v10 + fx*(v11 - v10);
        catp[32 + tx] = v0 + fy*(v1 - v0);
    }
    {
        float sy = y*0.125f - 0.4375f, sx = x*0.125f - 0.4375f;
        int y0 = (int)floorf(sy), x0 = (int)floorf(sx);
        float fy = sy - (float)y0, fx = sx - (float)x0;
        int y0c = max(y0, 0), y1c = min(y0 + 1, 23);
        int x0c = max(x0, 0), x1c = min(x0 + 1, 23);
        const float* base = &g_a32[(size_t)b*24*24*32];
        float v00 = base[(y0c*24 + x0c)*32 + tx];
        float v01 = base[(y0c*24 + x1c)*32 + tx];
        float v10 = base[(y1c*24 + x0c)*32 + tx];
        float v11 = base[(y1c*24 + x1c)*32 + tx];
        float v0 = v00 + fx*(v01 - v00);
        float v1 = v10 + fx*(v11 - v10);
        catp[64 + tx] = v0 + fy*(v1 - v0);
    }
}

// ---------------- 3x3 conv SAME + bias + relu : g_cat -> g_aspp -----------------
// 6y x 32x x 32co tile, 256 threads (6y x 4co per thread), ci staged in 2 halves
// of 48 so smem = 111.9 KB -> 2 CTAs/SM. Weights held in regs, input rows streamed.
#define CIH 48
#define CIS2 52
#define SIN2 (8*34*CIS2)            // 14144 floats
#define SW2  (9*CIH*32)             // 13824 floats
__global__ void __launch_bounds__(256, 2) k_conv3x3(const float* __restrict__ wf,
                                                    const float* __restrict__ bf)
{
    extern __shared__ float sm[];
    float* s_in = sm;               // [8][34][52]
    float* s_w  = sm + SIN2;        // [9][48][32]
    int tid = threadIdx.x;
    int cog = tid & 7;              // co group of 4
    int pxx = tid >> 3;             // 0..31 local x
    int xt = blockIdx.x % 6, cs = blockIdx.x / 6;
    int y0 = blockIdx.y * 6, b = blockIdx.z;
    int x0 = xt * 32;

    u64 zero = pack2(0.f, 0.f);
    u64 acc[6][2];
    #pragma unroll
    for (int i = 0; i < 6; i++) { acc[i][0] = zero; acc[i][1] = zero; }

    for (int h = 0; h < 2; h++) {
        if (h) __syncthreads();     // drain reads of previous half
        // stage weights for this ci half: s_w[(t*48+cil)*32 + l]
        for (int i = tid; i < 9*CIH*32; i += 256) {
            int l = i & 31, tci = i >> 5;      // tci = t*48 + cil
            int t = tci / CIH, cil = tci - t*CIH;
            s_w[tci*32 + l] = wf[(t*96 + h*CIH + cil)*96 + cs*32 + l];
        }
        // stage input rows y0-1..y0+6, x0-1..x0+32 for this ci half
        for (int i = tid; i < 8*34*12; i += 256) {
            int px = i / 12, c4 = i - px*12;
            int ry = px / 34, xl = px - ry*34;
            int yy = y0 + ry - 1;
            int xx = x0 + xl - 1;
            float4 v = make_float4(0.f, 0.f, 0.f, 0.f);
            if (yy >= 0 && yy < HF && xx >= 0 && xx < HF)
                v = *(const float4*)&g_cat[(((size_t)b*HF + yy)*HF + xx)*CC + h*CIH + c4*4];
            *(float4*)&s_in[px*CIS2 + c4*4] = v;
        }
        __syncthreads();

        #pragma unroll 1
        for (int cil = 0; cil < CIH; cil++) {
            ulonglong2 w[9];
            const float* wb = &s_w[cil*32 + cog*4];
            #pragma unroll
            for (int t = 0; t < 9; t++)
                w[t] = *(const ulonglong2*)&wb[t*CIH*32];
            #pragma unroll
            for (int ry = 0; ry < 8; ry++) {
                u64 a[3];
                #pragma unroll
                for (int dx = 0; dx < 3; dx++) {
                    float v = s_in[(ry*34 + pxx + dx)*CIS2 + cil];
                    a[dx] = pack2(v, v);
                }
                #pragma unroll
                for (int r = 0; r < 3; r++) {
                    int yo = ry - r;
                    if (yo >= 0 && yo < 6) {
                        #pragma unroll
                        for (int dx = 0; dx < 3; dx++) {
                            acc[yo][0] = fma2(a[dx], w[r*3 + dx].x, acc[yo][0]);
                            acc[yo][1] = fma2(a[dx], w[r*3 + dx].y, acc[yo][1]);
                        }
                    }
                }
            }
        }
    }

    int co0 = cs*32 + cog*4;
    float bv[4];
    #pragma unroll
    for (int j = 0; j < 4; j++) bv[j] = bf[co0 + j];
    #pragma unroll
    for (int yo = 0; yo < 6; yo++) {
        float o[4];
        #pragma unroll
        for (int j = 0; j < 2; j++) {
            float lo, hi; unpack2(acc[yo][j], lo, hi);
            o[2*j]   = fmaxf(lo + bv[2*j],   0.f);
            o[2*j+1] = fmaxf(hi + bv[2*j+1], 0.f);
        }
        float* op = &g_aspp[(((size_t)b*HF + y0 + yo)*HF + x0 + pxx)*CC + co0];
        *(float4*)op = make_float4(o[0], o[1], o[2], o[3]);
    }
}

// ---------------- precompute G[px][64] = aspp[px][96] @ W0_feat + b0 -----------------
// R8-proven: 64 px per block, 256 threads; thread = 2 co x 8 px (pairs over px)
#define SAS 66
__global__ void __launch_bounds__(256) k_precg(const float* __restrict__ mw0,
                                               const float* __restrict__ mb0)
{
    __shared__ float sw[96*64];     // [k][co]
    __shared__ float sa[96*SAS];    // [k][px] transposed
    int tid = threadIdx.x;
    int p0 = blockIdx.x * 64;

    for (int i = tid; i < 96*64; i += 256) sw[i] = mw0[i];
    for (int i = tid; i < 64*24; i += 256) {
        int px = i / 24, c4 = i - px*24;
        float4 v = *(const float4*)&g_aspp[(size_t)(p0 + px)*96 + c4*4];
        sa[(c4*4 + 0)*SAS + px] = v.x;
        sa[(c4*4 + 1)*SAS + px] = v.y;
        sa[(c4*4 + 2)*SAS + px] = v.z;
        sa[(c4*4 + 3)*SAS + px] = v.w;
    }
    __syncthreads();

    int cop = tid & 31;             // co pair: co = cop*2
    int pxg = tid >> 5;             // px base = pxg*8
    u64 zero = pack2(0.f, 0.f);
    u64 acc0[4] = {zero, zero, zero, zero};
    u64 acc1[4] = {zero, zero, zero, zero};

    #pragma unroll 4
    for (int k = 0; k < 96; k++) {
        float2 w = *(const float2*)&sw[k*64 + cop*2];
        u64 w0 = pack2(w.x, w.x), w1 = pack2(w.y, w.y);
        const u64* ap = (const u64*)&sa[k*SAS + pxg*8];
        #pragma unroll
        for (int j = 0; j < 4; j++) {
            u64 a = ap[j];
            acc0[j] = fma2(a, w0, acc0[j]);
            acc1[j] = fma2(a, w1, acc1[j]);
        }
    }

    float b0v = mb0[cop*2], b1v = mb0[cop*2 + 1];
    #pragma unroll
    for (int j = 0; j < 4; j++) {
        float a_lo, a_hi, b_lo, b_hi;
        unpack2(acc0[j], a_lo, a_hi);
        unpack2(acc1[j], b_lo, b_hi);
        int px = p0 + pxg*8 + 2*j;
        *(float2*)&g_G[(size_t)px*64 + cop*2]       = make_float2(a_lo + b0v, b_lo + b1v);
        *(float2*)&g_G[(size_t)(px + 1)*64 + cop*2] = make_float2(a_hi + b0v, b_hi + b1v);
    }
}

// ---------------- fused gather + tiny-MLP + area combine (R8-proven) -----------------
#define HS 65
#define QPB 64
#define ROWS 256
__global__ void __launch_bounds__(256, 2) k_mlp(
    const float* __restrict__ coords, const float* __restrict__ cells,
    const float* __restrict__ mw0, const float* __restrict__ mb0,
    const float* __restrict__ mw1, const float* __restrict__ mb1,
    const float* __restrict__ mw2, const float* __restrict__ mb2,
    float* __restrict__ out)
{
    extern __shared__ float sm[];
    float* s_w0s  = sm;                    // 384
    float* s_w1   = s_w0s + 384;           // 4096
    float* s_b1   = s_w1 + 4096;           // 64
    float* s_w2   = s_b1 + 64;             // 64
    float* s_sc   = s_w2 + 64;             // 256*8 scalars
    float* s_area = s_sc + ROWS*8;         // 256
    float* s_h    = s_area + ROWS;         // 256*65
    float* s_part = s_h + ROWS*HS;         // 256*8
    float* s_pred = s_part + ROWS*8;       // 256
    int*   s_pix  = (int*)(s_pred + ROWS); // 256

    int tid = threadIdx.x;
    for (int i = tid; i < 384; i += 256) s_w0s[i] = mw0[96*64 + i];
    for (int i = tid; i < 4096; i += 256) s_w1[i] = mw1[i];
    if (tid < 64) { s_b1[tid] = mb1[tid]; s_w2[tid] = mw2[tid]; }

    int q0 = blockIdx.x * QPB;

    // ---- Phase A ----
    {
        int r = tid;
        int q = q0 + (r >> 2), c = r & 3;
        int bq = q / (384*384);
        float cy = coords[q*2], cx = coords[q*2 + 1];
        float vy = (c & 2) ? 1.f : -1.f;
        float vx = (c & 1) ? 1.f : -1.f;
        const float RX = 1.0f/192.0f;
        float fy = __fadd_rn(__fadd_rn(cy, __fmul_rn(vy, RX)), EPSC);
        float fx = __fadd_rn(__fadd_rn(cx, __fmul_rn(vx, RX)), EPSC);
        fy = fminf(fmaxf(fy, -1.f + EPSC), 1.f - EPSC);
        fx = fminf(fmaxf(fx, -1.f + EPSC), 1.f - EPSC);
        float tyf = __fadd_rn(__fmul_rn(__fmul_rn(__fadd_rn(fy, 1.f), 192.f), 0.5f), -0.5f);
        float txf = __fadd_rn(__fmul_rn(__fmul_rn(__fadd_rn(fx, 1.f), 192.f), 0.5f), -0.5f);
        int iy = min(max((int)rintf(tyf), 0), 191);
        int ix = min(max((int)rintf(txf), 0), 191);

        s_pix[r] = (bq*HF + iy)*HF + ix;

        float csy = __fadd_rn(__fmul_rn(__fdiv_rn(__fadd_rn((float)iy, 0.5f), 192.f), 2.f), -1.f);
        float csx = __fadd_rn(__fmul_rn(__fdiv_rn(__fadd_rn((float)ix, 0.5f), 192.f), 2.f), -1.f);
        float ry = __fmul_rn(__fsub_rn(cy, csy), 192.f);
        float rx = __fmul_rn(__fsub_rn(cx, csx), 192.f);
        float rcy = __fmul_rn(cells[q*2],     192.f);
        float rcx = __fmul_rn(cells[q*2 + 1], 192.f);
        float* sc = &s_sc[r*8];
        sc[0] = ry; sc[1] = rx; sc[2] = cy; sc[3] = cx; sc[4] = rcy; sc[5] = rcx;
        s_area[r] = fabsf(__fmul_rn(ry, rx)) + EPSC;
    }
    __syncthreads();

    int tx8 = tid & 7, tyr = tid >> 3;
    int R0 = tyr * 8;
    u64 zero = pack2(0.f, 0.f);

    // ---- Layer 1: h = relu(G[pix] + scal(6) @ W0s) ----
    {
        u64 acc[8][4];
        #pragma unroll
        for (int i = 0; i < 8; i++) {
            const u64* gp = (const u64*)&g_G[(size_t)s_pix[R0 + i]*64 + tx8*8];
            #pragma unroll
            for (int j = 0; j < 4; j++) acc[i][j] = gp[j];
        }
        #pragma unroll
        for (int s = 0; s < 6; s++) {
            const ulonglong2* wp = (const ulonglong2*)&s_w0s[s*64 + tx8*8];
            ulonglong2 w01 = wp[0], w23 = wp[1];
            #pragma unroll
            for (int i = 0; i < 8; i++) {
                float a = s_sc[(R0 + i)*8 + s];
                u64 ap = pack2(a, a);
                acc[i][0] = fma2(ap, w01.x, acc[i][0]);
                acc[i][1] = fma2(ap, w01.y, acc[i][1]);
                acc[i][2] = fma2(ap, w23.x, acc[i][2]);
                acc[i][3] = fma2(ap, w23.y, acc[i][3]);
            }
        }
        #pragma unroll
        for (int i = 0; i < 8; i++) {
            int row = R0 + i;
            #pragma unroll
            for (int j = 0; j < 4; j++) {
                float lo, hi; unpack2(acc[i][j], lo, hi);
                int c = tx8*8 + 2*j;
                s_h[row*HS + c]     = fmaxf(lo, 0.f);
                s_h[row*HS + c + 1] = fmaxf(hi, 0.f);
            }
        }
    }
    __syncthreads();

    // ---- Layer 2 + fold with w2 ----
    {
        u64 acc[8][4];
        #pragma unroll
        for (int i = 0; i < 8; i++)
            #pragma unroll
            for (int j = 0; j < 4; j++) acc[i][j] = zero;
        const float* hb = &s_h[R0*HS];
        #pragma unroll 4
        for (int k = 0; k < 64; k++) {
            const ulonglong2* wp = (const ulonglong2*)&s_w1[k*64 + tx8*8];
            ulonglong2 w01 = wp[0], w23 = wp[1];
            #pragma unroll
            for (int i = 0; i < 8; i++) {
                float a = hb[i*HS + k];
                u64 ap = pack2(a, a);
                acc[i][0] = fma2(ap, w01.x, acc[i][0]);
                acc[i][1] = fma2(ap, w01.y, acc[i][1]);
                acc[i][2] = fma2(ap, w23.x, acc[i][2]);
                acc[i][3] = fma2(ap, w23.y, acc[i][3]);
            }
        }
        #pragma unroll
        for (int i = 0; i < 8; i++) {
            int row = R0 + i;
            float part = 0.f;
            #pragma unroll
            for (int j = 0; j < 4; j++) {
                float lo, hi; unpack2(acc[i][j], lo, hi);
                int c = tx8*8 + 2*j;
                part = fmaf(fmaxf(lo + s_b1[c],     0.f), s_w2[c],     part);
                part = fmaf(fmaxf(hi + s_b1[c + 1], 0.f), s_w2[c + 1], part);
            }
            s_part[row*8 + tx8] = part;
        }
    }
    __syncthreads();

    {
        float p = mb2[0];
        #pragma unroll
        for (int j = 0; j < 8; j++) p += s_part[tid*8 + j];
        s_pred[tid] = p;
    }
    __syncthreads();

    if (tid < QPB) {
        int r = tid*4;
        float a0 = s_area[r], a1 = s_area[r+1], a2 = s_area[r+2], a3 = s_area[r+3];
        float p0 = s_pred[r], p1 = s_pred[r+1], p2 = s_pred[r+2], p3 = s_pred[r+3];
        float num = p0*a3 + p1*a2 + p2*a1 + p3*a0;
        float den = a3 + a2 + a1 + a0;
        out[q0 + tid] = num / den;
    }
}

extern "C" void kernel_launch(void* const* d_in, const int* in_sizes, int n_in,
                              void* d_out, int out_size)
{
    const float* feats2 = (const float*)d_in[0];
    const float* feats4 = (const float*)d_in[1];
    const float* feats32= (const float*)d_in[2];
    const float* coords = (const float*)d_in[3];
    const float* cells  = (const float*)d_in[4];
    const float* w2  = (const float*)d_in[5];
    const float* b2  = (const float*)d_in[6];
    const float* w4  = (const float*)d_in[7];
    const float* b4  = (const float*)d_in[8];
    const float* w32 = (const float*)d_in[9];
    const float* b32 = (const float*)d_in[10];
    const float* wf  = (const float*)d_in[11];
    const float* bf  = (const float*)d_in[12];
    const float* mw0 = (const float*)d_in[13];
    const float* mb0 = (const float*)d_in[14];
    const float* mw1 = (const float*)d_in[15];
    const float* mb1 = (const float*)d_in[16];
    const float* mw2 = (const float*)d_in[17];
    const float* mb2 = (const float*)d_in[18];
    float* out = (float*)d_out;

    dim3 blk(32, 8);

    k_conv1x1<<<NB*96*96/8, blk, (96*32 + 8*96)*sizeof(float)>>>(feats4, w4, b4, NB*96*96, 96, 0);
    k_conv1x1<<<NB*24*24/8, blk, (160*32 + 8*160)*sizeof(float)>>>(feats32, w32, b32, NB*24*24, 160, 1);

    k_build_cat<<<dim3(HF/16, HF, NB), dim3(32, 16)>>>(feats2, w2, b2);

    // 3x3 conv: 6y x 32x px tile, 32-co set, 256 threads, ci-split -> 2 CTAs/SM
    size_t smem3 = (size_t)(SIN2 + SW2) * sizeof(float);   // 111872 B
    cudaFuncSetAttribute(k_conv3x3, cudaFuncAttributeMaxDynamicSharedMemorySize, (int)smem3);
    k_conv3x3<<<dim3(6*3, 32, NB), 256, smem3>>>(wf, bf);

    // precompute G = aspp @ W0_feat + b0 : 64 px/block (R8-proven)
    k_precg<<<NB*HF*HF/64, 256>>>(mw0, mb0);

    // fused gather + tiny MLP: 64 queries/block, 256 threads, 2 CTAs/SM
    size_t smemM = (size_t)(384 + 4096 + 64 + 64 + ROWS*8 + ROWS + ROWS*HS + ROWS*8 + ROWS + ROWS) * sizeof(float);
    cudaFuncSetAttribute(k_mlp, cudaFuncAttributeMaxDynamicSharedMemorySize, (int)smemM);
    k_mlp<<<(NB*384*384)/QPB, 256, smemM>>>(coords, cells, mw0, mb0, mw1, mb1, mw2, mb2, out);
}

// round 15
// speedup vs baseline: 1.3675x; 1.2270x over previous
#include <cuda_runtime.h>
#include <cuda_bf16.h>
#include <cstdint>

typedef unsigned long long u64;
#define DI __device__ __forceinline__

DI u64 pack2(float a, float b){ u64 r; asm("mov.b64 %0, {%1,%2};" : "=l"(r) : "f"(a), "f"(b)); return r; }
DI void unpack2(u64 v, float &a, float &b){ asm("mov.b64 {%0,%1}, %2;" : "=f"(a), "=f"(b) : "l"(v)); }
DI u64 fma2(u64 a, u64 b, u64 c){ u64 d; asm("fma.rn.f32x2 %0, %1, %2, %3;" : "=l"(d) : "l"(a), "l"(b), "l"(c)); return d; }

#define NB 2
#define HF 192
#define CC 96
#define EPSC 1e-7f

DI uint32_t smem_to_u32(const void* p) {
    uint32_t a;
    asm("{ .reg .u64 t; cvta.to.shared.u64 t, %1; cvt.u32.u64 %0, t; }" : "=r"(a) : "l"(p));
    return a;
}
DI void ldm_x4(uint32_t* r, uint32_t addr){
    asm volatile("ldmatrix.sync.aligned.m8n8.x4.shared.b16 {%0,%1,%2,%3}, [%4];"
        : "=r"(r[0]), "=r"(r[1]), "=r"(r[2]), "=r"(r[3]) : "r"(addr));
}
DI void mma16816(float* c, const uint32_t* a, const uint32_t* b){
    asm volatile("mma.sync.aligned.m16n8k16.row.col.f32.bf16.bf16.f32 "
        "{%0,%1,%2,%3}, {%4,%5,%6,%7}, {%8,%9}, {%0,%1,%2,%3};"
        : "+f"(c[0]), "+f"(c[1]), "+f"(c[2]), "+f"(c[3])
        : "r"(a[0]), "r"(a[1]), "r"(a[2]), "r"(a[3]), "r"(b[0]), "r"(b[1]));
}

// ---------------- globals ----------------
__device__ float g_a4 [NB*96*96*32];
__device__ float g_a32[NB*24*24*32];
__device__ __nv_bfloat16 g_cbf[(size_t)2*NB*HF*HF*CC];   // hi/lo planes of concat grid
__device__ __nv_bfloat16 g_wb [(size_t)2*9*96*128];      // hi/lo weights [s][t][co][128ci]
__device__ float g_aspp[NB*HF*HF*CC];
__device__ float g_G   [NB*HF*HF*64];

// ---------------- 1x1 conv + bias + relu (feats4 -> a4, feats32 -> a32) -------------
__global__ void k_conv1x1(const float* __restrict__ in, const float* __restrict__ w,
                          const float* __restrict__ bias, int npix, int cin, int which)
{
    extern __shared__ float sm[];
    float* sw  = sm;
    float* spx = sm + cin*32;
    int tx = threadIdx.x, ty = threadIdx.y;
    int tid = ty*32 + tx;
    for (int i = tid; i < cin*32; i += 256) sw[i] = w[i];
    int p = blockIdx.x*8 + ty;
    for (int ci = tx; ci < cin; ci += 32)
        spx[ty*cin + ci] = (p < npix) ? in[p*cin + ci] : 0.f;
    __syncthreads();
    if (p >= npix) return;
    float acc = bias[tx];
    const float* sp = spx + ty*cin;
    #pragma unroll 4
    for (int ci = 0; ci < cin; ci++)
        acc = fmaf(sp[ci], sw[ci*32 + tx], acc);
    float* outp = which ? g_a32 : g_a4;
    outp[p*32 + tx] = fmaxf(acc, 0.f);
}

// ---------------- weight prep: fp32 -> bf16 hi/lo, [s][t][co][128ci] ----------------
__global__ void k_wprep(const float* __restrict__ wf)
{
    int idx = blockIdx.x*256 + threadIdx.x;
    if (idx >= 9*96*128) return;
    int ci = idx & 127;
    int rest = idx >> 7;
    int co = rest % 96, t = rest / 96;
    float v = (ci < 96) ? wf[(t*96 + ci)*96 + co] : 0.f;
    __nv_bfloat16 hi = __float2bfloat16(v);
    __nv_bfloat16 lo = __float2bfloat16(v - __bfloat162float(hi));
    size_t o = ((size_t)t*96 + co)*128 + ci;
    g_wb[o] = hi;
    g_wb[(size_t)9*96*128 + o] = lo;
}

// ------------- build concat grid (bf16 hi/lo planes) : 16 px per block, 512 threads ----
DI void store_hl(size_t idx, float v)
{
    __nv_bfloat16 hi = __float2bfloat16(v);
    g_cbf[idx] = hi;
    g_cbf[(size_t)NB*HF*HF*CC + idx] = __float2bfloat16(v - __bfloat162float(hi));
}

__global__ void __launch_bounds__(512) k_build_cat(const float* __restrict__ feats2,
                            const float* __restrict__ w2, const float* __restrict__ b2)
{
    __shared__ float sw[64*32];
    __shared__ float spx[16][64];
    int tx = threadIdx.x, ty = threadIdx.y;
    int tid = ty*32 + tx;
    for (int i = tid; i < 64*32; i += 512) sw[i] = w2[i];
    int b = blockIdx.z, y = blockIdx.y, x = blockIdx.x*16 + ty;
    int pix = (b*HF + y)*HF + x;
    spx[ty][tx]      = feats2[pix*64 + tx];
    spx[ty][tx + 32] = feats2[pix*64 + tx + 32];
    __syncthreads();

    size_t base = (size_t)pix*CC;
    {
        float acc = b2[tx];
        #pragma unroll 8
        for (int ci = 0; ci < 64; ci++)
            acc = fmaf(spx[ty][ci], sw[ci*32 + tx], acc);
        store_hl(base + tx, fmaxf(acc, 0.f));
    }
    {
        float sy = y*0.5f - 0.25f, sx = x*0.5f - 0.25f;
        int y0 = (int)floorf(sy), x0 = (int)floorf(sx);
        float fy = sy - (float)y0, fx = sx - (float)x0;
        int y0c = max(y0, 0), y1c = min(y0 + 1, 95);
        int x0c = max(x0, 0), x1c = min(x0 + 1, 95);
        const float* bse = &g_a4[(size_t)b*96*96*32];
        float v00 = bse[(y0c*96 + x0c)*32 + tx];
        float v01 = bse[(y0c*96 + x1c)*32 + tx];
        float v10 = bse[(y1c*96 + x0c)*32 + tx];
        float v11 = bse[(y1c*96 + x1c)*32 + tx];
        float v0 = v00 + fx*(v01 - v00);
        float v1 = v10 + fx*(v11 - v10);
        store_hl(base + 32 + tx, v0 + fy*(v1 - v0));
    }
    {
        float sy = y*0.125f - 0.4375f, sx = x*0.125f - 0.4375f;
        int y0 = (int)floorf(sy), x0 = (int)floorf(sx);
        float fy = sy - (float)y0, fx = sx - (float)x0;
        int y0c = max(y0, 0), y1c = min(y0 + 1, 23);
        int x0c = max(x0, 0), x1c = min(x0 + 1, 23);
        const float* bse = &g_a32[(size_t)b*24*24*32];
        float v00 = bse[(y0c*24 + x0c)*32 + tx];
        float v01 = bse[(y0c*24 + x1c)*32 + tx];
        float v10 = bse[(y1c*24 + x0c)*32 + tx];
        float v11 = bse[(y1c*24 + x1c)*32 + tx];
        float v0 = v00 + fx*(v01 - v00);
        float v1 = v10 + fx*(v11 - v10);
        store_hl(base + 64 + tx, v0 + fy*(v1 - v0));
    }
}

// ---------------- 3x3 conv via mma.sync bf16 hi/lo (fp32 accum) ----------------
// Block: 128 px (4y x 32x) x 96 co, 256 threads / 8 warps.
// Warp w: px 16w..16w+15, all 96 co (12 n-tiles of 8). 9 taps x 3 split-combos.
#define AST 104                      // bf16 stride per (row,x): conflict-free for ldmatrix
#define SM_BIAS 0
#define SM_A 512
#define SM_A_BYTES (2*6*34*AST*2)    // 84864
#define SM_W (SM_A + SM_A_BYTES)     // 85376
#define SM_W_BYTES (2*96*AST*2)      // 39936
#define SM_TOTAL (SM_W + SM_W_BYTES) // 125312

__global__ void __launch_bounds__(256, 1) k_conv3x3_mma(const float* __restrict__ bf)
{
    extern __shared__ char smem[];
    uint32_t smem_base = smem_to_u32(smem);
    float* s_bias = (float*)(smem + SM_BIAS);
    __nv_bfloat16* s_a = (__nv_bfloat16*)(smem + SM_A);
    int tid = threadIdx.x;
    int w = tid >> 5, lane = tid & 31;
    int x0 = blockIdx.x*32, y0 = blockIdx.y*4, b = blockIdx.z;

    if (tid < 96) s_bias[tid] = bf[tid];

    // stage halo: [s][6 rows][34 x][96 ci] bf16, stride 104
    for (int i = tid; i < 2*6*34*12; i += 256) {
        int ci0 = (i % 12)*8;
        int px = i / 12;
        int hx = px % 34;
        int rem = px / 34;
        int row = rem % 6, s = rem / 6;
        int yy = y0 - 1 + row, xx = x0 - 1 + hx;
        uint4 v = make_uint4(0,0,0,0);
        if (yy >= 0 && yy < HF && xx >= 0 && xx < HF)
            v = *(const uint4*)&g_cbf[(size_t)s*NB*HF*HF*CC + (((size_t)b*HF + yy)*HF + xx)*CC + ci0];
        *(uint4*)&s_a[((s*6 + row)*34 + hx)*AST + ci0] = v;
    }

    float acc[12][4];
    #pragma unroll
    for (int t = 0; t < 12; t++)
        #pragma unroll
        for (int j = 0; j < 4; j++) acc[t][j] = 0.f;

    int jm = lane >> 3, rr = lane & 7;           // ldmatrix sub-matrix index / row
    // A-frag lane geometry (fixed across taps up to (r,dx) shift)
    int apx = w*16 + (jm & 1)*8 + rr;            // px row for this lane's matrix
    int ay_b = apx >> 5, ax_b = apx & 31;
    int akoff = (jm >> 1)*8;
    uint32_t aw_base = smem_base + SM_A;
    uint32_t ww_base = smem_base + SM_W;

    for (int tap = 0; tap < 9; tap++) {
        int r = tap/3, dx = tap%3;
        __syncthreads();            // prior tap's reads done before restaging weights
        // stage weights for this tap: [s][96 co][ci 0..95] bf16 stride 104
        for (int i = tid; i < 2*96*12; i += 256) {
            int s = (i >= 96*12) ? 1 : 0;
            int i2 = i - s*96*12;
            int co = i2 / 12, c4 = i2 % 12;
            uint4 v = *(const uint4*)&g_wb[(size_t)s*9*96*128 + ((size_t)tap*96 + co)*128 + c4*8];
            *(uint4*)(smem + SM_W + ((s*96 + co)*AST + c4*8)*2) = v;
        }
        __syncthreads();

        uint32_t a_hi_base = aw_base + (uint32_t)((((0*6 + ay_b + r)*34 + ax_b + dx)*AST + akoff)*2);
        uint32_t a_lo_base = a_hi_base + (uint32_t)(6*34*AST*2);

        #pragma unroll 1
        for (int k0 = 0; k0 < 96; k0 += 16) {
            uint32_t ah[4], al[4];
            ldm_x4(ah, a_hi_base + (uint32_t)(k0*2));
            ldm_x4(al, a_lo_base + (uint32_t)(k0*2));
            #pragma unroll
            for (int cp = 0; cp < 6; cp++) {
                // B lane geometry (non-trans, weights are [n][k]):
                // jm0: n-tile-lo rows @k0, jm1: n-tile-lo @k8, jm2: n-tile-hi @k0, jm3: n-tile-hi @k8
                int co_row = (cp*2 + (jm >> 1))*8 + rr;
                int kk = k0 + (jm & 1)*8;
                uint32_t bh_addr = ww_base + (uint32_t)((co_row*AST + kk)*2);
                uint32_t bl_addr = bh_addr + (uint32_t)(96*AST*2);
                uint32_t bh[4], bl[4];
                ldm_x4(bh, bh_addr);
                ldm_x4(bl, bl_addr);
                int t0 = cp*2, t1 = cp*2 + 1;
                mma16816(acc[t0], ah, bh);
                mma16816(acc[t0], ah, bl);
                mma16816(acc[t0], al, bh);
                mma16816(acc[t1], ah, bh + 2);
                mma16816(acc[t1], ah, bl + 2);
                mma16816(acc[t1], al, bh + 2);
            }
        }
    }

    // epilogue: C frag rows = px (w*16 + gid, +8), cols = cot*8 + tig*2 (+1)
    int gid = lane >> 2, tig = lane & 3;
    int px0 = w*16 + gid;
    int ya = y0 + (px0 >> 5), xa = x0 + (px0 & 31);
    int px1 = px0 + 8;
    int yb = y0 + (px1 >> 5), xb = x0 + (px1 & 31);
    float* op0 = &g_aspp[(((size_t)b*HF + ya)*HF + xa)*CC];
    float* op1 = &g_aspp[(((size_t)b*HF + yb)*HF + xb)*CC];
    #pragma unroll
    for (int t = 0; t < 12; t++) {
        int c = t*8 + tig*2;
        float b0v = s_bias[c], b1v = s_bias[c + 1];
        *(float2*)&op0[c] = make_float2(fmaxf(acc[t][0] + b0v, 0.f), fmaxf(acc[t][1] + b1v, 0.f));
        *(float2*)&op1[c] = make_float2(fmaxf(acc[t][2] + b0v, 0.f), fmaxf(acc[t][3] + b1v, 0.f));
    }
}

// ---------------- precompute G[px][64] = aspp[px][96] @ W0_feat + b0 -----------------
#define SAS 66
__global__ void __launch_bounds__(256) k_precg(const float* __restrict__ mw0,
                                               const float* __restrict__ mb0)
{
    __shared__ float sw[96*64];
    __shared__ float sa[96*SAS];
    int tid = threadIdx.x;
    int p0 = blockIdx.x * 64;

    for (int i = tid; i < 96*64; i += 256) sw[i] = mw0[i];
    for (int i = tid; i < 64*24; i += 256) {
        int px = i / 24, c4 = i - px*24;
        float4 v = *(const float4*)&g_aspp[(size_t)(p0 + px)*96 + c4*4];
        sa[(c4*4 + 0)*SAS + px] = v.x;
        sa[(c4*4 + 1)*SAS + px] = v.y;
        sa[(c4*4 + 2)*SAS + px] = v.z;
        sa[(c4*4 + 3)*SAS + px] = v.w;
    }
    __syncthreads();

    int cop = tid & 31;
    int pxg = tid >> 5;
    u64 zero = pack2(0.f, 0.f);
    u64 acc0[4] = {zero, zero, zero, zero};
    u64 acc1[4] = {zero, zero, zero, zero};

    #pragma unroll 4
    for (int k = 0; k < 96; k++) {
        float2 w = *(const float2*)&sw[k*64 + cop*2];
        u64 w0 = pack2(w.x, w.x), w1 = pack2(w.y, w.y);
        const u64* ap = (const u64*)&sa[k*SAS + pxg*8];
        #pragma unroll
        for (int j = 0; j < 4; j++) {
            u64 a = ap[j];
            acc0[j] = fma2(a, w0, acc0[j]);
            acc1[j] = fma2(a, w1, acc1[j]);
        }
    }

    float b0v = mb0[cop*2], b1v = mb0[cop*2 + 1];
    #pragma unroll
    for (int j = 0; j < 4; j++) {
        float a_lo, a_hi, b_lo, b_hi;
        unpack2(acc0[j], a_lo, a_hi);
        unpack2(acc1[j], b_lo, b_hi);
        int px = p0 + pxg*8 + 2*j;
        *(float2*)&g_G[(size_t)px*64 + cop*2]       = make_float2(a_lo + b0v, b_lo + b1v);
        *(float2*)&g_G[(size_t)(px + 1)*64 + cop*2] = make_float2(a_hi + b0v, b_hi + b1v);
    }
}

// ---------------- fused gather + tiny-MLP + area combine (R8/R11-proven) -----------------
#define HS 65
#define QPB 64
#define ROWS 256
__global__ void __launch_bounds__(256, 2) k_mlp(
    const float* __restrict__ coords, const float* __restrict__ cells,
    const float* __restrict__ mw0, const float* __restrict__ mb0,
    const float* __restrict__ mw1, const float* __restrict__ mb1,
    const float* __restrict__ mw2, const float* __restrict__ mb2,
    float* __restrict__ out)
{
    extern __shared__ float sm[];
    float* s_w0s  = sm;                    // 384
    float* s_w1   = s_w0s + 384;           // 4096
    float* s_b1   = s_w1 + 4096;           // 64
    float* s_w2   = s_b1 + 64;             // 64
    float* s_sc   = s_w2 + 64;             // 256*8
    float* s_area = s_sc + ROWS*8;         // 256
    float* s_h    = s_area + ROWS;         // 256*65
    float* s_part = s_h + ROWS*HS;         // 256*8
    float* s_pred = s_part + ROWS*8;       // 256
    int*   s_pix  = (int*)(s_pred + ROWS); // 256

    int tid = threadIdx.x;
    for (int i = tid; i < 384; i += 256) s_w0s[i] = mw0[96*64 + i];
    for (int i = tid; i < 4096; i += 256) s_w1[i] = mw1[i];
    if (tid < 64) { s_b1[tid] = mb1[tid]; s_w2[tid] = mw2[tid]; }

    int q0 = blockIdx.x * QPB;

    {
        int r = tid;
        int q = q0 + (r >> 2), c = r & 3;
        int bq = q / (384*384);
        float cy = coords[q*2], cx = coords[q*2 + 1];
        float vy = (c & 2) ? 1.f : -1.f;
        float vx = (c & 1) ? 1.f : -1.f;
        const float RX = 1.0f/192.0f;
        float fy = __fadd_rn(__fadd_rn(cy, __fmul_rn(vy, RX)), EPSC);
        float fx = __fadd_rn(__fadd_rn(cx, __fmul_rn(vx, RX)), EPSC);
        fy = fminf(fmaxf(fy, -1.f + EPSC), 1.f - EPSC);
        fx = fminf(fmaxf(fx, -1.f + EPSC), 1.f - EPSC);
        float tyf = __fadd_rn(__fmul_rn(__fmul_rn(__fadd_rn(fy, 1.f), 192.f), 0.5f), -0.5f);
        float txf = __fadd_rn(__fmul_rn(__fmul_rn(__fadd_rn(fx, 1.f), 192.f), 0.5f), -0.5f);
        int iy = min(max((int)rintf(tyf), 0), 191);
        int ix = min(max((int)rintf(txf), 0), 191);

        s_pix[r] = (bq*HF + iy)*HF + ix;

        float csy = __fadd_rn(__fmul_rn(__fdiv_rn(__fadd_rn((float)iy, 0.5f), 192.f), 2.f), -1.f);
        float csx = __fadd_rn(__fmul_rn(__fdiv_rn(__fadd_rn((float)ix, 0.5f), 192.f), 2.f), -1.f);
        float ry = __fmul_rn(__fsub_rn(cy, csy), 192.f);
        float rx = __fmul_rn(__fsub_rn(cx, csx), 192.f);
        float rcy = __fmul_rn(cells[q*2],     192.f);
        float rcx = __fmul_rn(cells[q*2 + 1], 192.f);
        float* sc = &s_sc[r*8];
        sc[0] = ry; sc[1] = rx; sc[2] = cy; sc[3] = cx; sc[4] = rcy; sc[5] = rcx;
        s_area[r] = fabsf(__fmul_rn(ry, rx)) + EPSC;
    }
    __syncthreads();

    int tx8 = tid & 7, tyr = tid >> 3;
    int R0 = tyr * 8;
    u64 zero = pack2(0.f, 0.f);

    {
        u64 acc[8][4];
        #pragma unroll
        for (int i = 0; i < 8; i++) {
            const u64* gp = (const u64*)&g_G[(size_t)s_pix[R0 + i]*64 + tx8*8];
            #pragma unroll
            for (int j = 0; j < 4; j++) acc[i][j] = gp[j];
        }
        #pragma unroll
        for (int s = 0; s < 6; s++) {
            const ulonglong2* wp = (const ulonglong2*)&s_w0s[s*64 + tx8*8];
            ulonglong2 w01 = wp[0], w23 = wp[1];
            #pragma unroll
            for (int i = 0; i < 8; i++) {
                float a = s_sc[(R0 + i)*8 + s];
                u64 ap = pack2(a, a);
                acc[i][0] = fma2(ap, w01.x, acc[i][0]);
                acc[i][1] = fma2(ap, w01.y, acc[i][1]);
                acc[i][2] = fma2(ap, w23.x, acc[i][2]);
                acc[i][3] = fma2(ap, w23.y, acc[i][3]);
            }
        }
        #pragma unroll
        for (int i = 0; i < 8; i++) {
            int row = R0 + i;
            #pragma unroll
            for (int j = 0; j < 4; j++) {
                float lo, hi; unpack2(acc[i][j], lo, hi);
                int c = tx8*8 + 2*j;
                s_h[row*HS + c]     = fmaxf(lo, 0.f);
                s_h[row*HS + c + 1] = fmaxf(hi, 0.f);
            }
        }
    }
    __syncthreads();

    {
        u64 acc[8][4];
        #pragma unroll
        for (int i = 0; i < 8; i++)
            #pragma unroll
            for (int j = 0; j < 4; j++) acc[i][j] = zero;
        const float* hb = &s_h[R0*HS];
        #pragma unroll 4
        for (int k = 0; k < 64; k++) {
            const ulonglong2* wp = (const ulonglong2*)&s_w1[k*64 + tx8*8];
            ulonglong2 w01 = wp[0], w23 = wp[1];
            #pragma unroll
            for (int i = 0; i < 8; i++) {
                float a = hb[i*HS + k];
                u64 ap = pack2(a, a);
                acc[i][0] = fma2(ap, w01.x, acc[i][0]);
                acc[i][1] = fma2(ap, w01.y, acc[i][1]);
                acc[i][2] = fma2(ap, w23.x, acc[i][2]);
                acc[i][3] = fma2(ap, w23.y, acc[i][3]);
            }
        }
        #pragma unroll
        for (int i = 0; i < 8; i++) {
            int row = R0 + i;
            float part = 0.f;
            #pragma unroll
            for (int j = 0; j < 4; j++) {
                float lo, hi; unpack2(acc[i][j], lo, hi);
                int c = tx8*8 + 2*j;
                part = fmaf(fmaxf(lo + s_b1[c],     0.f), s_w2[c],     part);
                part = fmaf(fmaxf(hi + s_b1[c + 1], 0.f), s_w2[c + 1], part);
            }
            s_part[row*8 + tx8] = part;
        }
    }
    __syncthreads();

    {
        float p = mb2[0];
        #pragma unroll
        for (int j = 0; j < 8; j++) p += s_part[tid*8 + j];
        s_pred[tid] = p;
    }
    __syncthreads();

    if (tid < QPB) {
        int r = tid*4;
        float a0 = s_area[r], a1 = s_area[r+1], a2 = s_area[r+2], a3 = s_area[r+3];
        float p0 = s_pred[r], p1 = s_pred[r+1], p2 = s_pred[r+2], p3 = s_pred[r+3];
        float num = p0*a3 + p1*a2 + p2*a1 + p3*a0;
        float den = a3 + a2 + a1 + a0;
        out[q0 + tid] = num / den;
    }
}

extern "C" void kernel_launch(void* const* d_in, const int* in_sizes, int n_in,
                              void* d_out, int out_size)
{
    const float* feats2 = (const float*)d_in[0];
    const float* feats4 = (const float*)d_in[1];
    const float* feats32= (const float*)d_in[2];
    const float* coords = (const float*)d_in[3];
    const float* cells  = (const float*)d_in[4];
    const float* w2  = (const float*)d_in[5];
    const float* b2  = (const float*)d_in[6];
    const float* w4  = (const float*)d_in[7];
    const float* b4  = (const float*)d_in[8];
    const float* w32 = (const float*)d_in[9];
    const float* b32 = (const float*)d_in[10];
    const float* wf  = (const float*)d_in[11];
    const float* bf  = (const float*)d_in[12];
    const float* mw0 = (const float*)d_in[13];
    const float* mb0 = (const float*)d_in[14];
    const float* mw1 = (const float*)d_in[15];
    const float* mb1 = (const float*)d_in[16];
    const float* mw2 = (const float*)d_in[17];
    const float* mb2 = (const float*)d_in[18];
    float* out = (float*)d_out;

    dim3 blk(32, 8);

    k_conv1x1<<<NB*96*96/8, blk, (96*32 + 8*96)*sizeof(float)>>>(feats4, w4, b4, NB*96*96, 96, 0);
    k_conv1x1<<<NB*24*24/8, blk, (160*32 + 8*160)*sizeof(float)>>>(feats32, w32, b32, NB*24*24, 160, 1);

    // weight hi/lo prep (independent)
    k_wprep<<<(9*96*128 + 255)/256, 256>>>(wf);

    // concat grid (bf16 hi/lo planes)
    k_build_cat<<<dim3(HF/16, HF, NB), dim3(32, 16)>>>(feats2, w2, b2);

    // 3x3 conv via mma.sync: 128 px x 96 co per block
    cudaFuncSetAttribute(k_conv3x3_mma, cudaFuncAttributeMaxDynamicSharedMemorySize, SM_TOTAL);
    k_conv3x3_mma<<<dim3(HF/32, HF/4, NB), 256, SM_TOTAL>>>(bf);

    // precompute G = aspp @ W0_feat + b0 : 64 px/block
    k_precg<<<NB*HF*HF/64, 256>>>(mw0, mb0);

    // fused gather + tiny MLP: 64 queries/block, 256 threads, 2 CTAs/SM
    size_t smemM = (size_t)(384 + 4096 + 64 + 64 + ROWS*8 + ROWS + ROWS*HS + ROWS*8 + ROWS + ROWS) * sizeof(float);
    cudaFuncSetAttribute(k_mlp, cudaFuncAttributeMaxDynamicSharedMemorySize, (int)smemM);
    k_mlp<<<(NB*384*384)/QPB, 256, smemM>>>(coords, cells, mw0, mb0, mw1, mb1, mw2, mb2, out);
}